// round 17
// baseline (speedup 1.0000x reference)
#include <cuda_runtime.h>
#include <cuda_bf16.h>
#include <cstdint>
#include <cstddef>

#define Bb    2
#define Tt    2048
#define Ee    1024
#define HQn   16
#define HKVn  4
#define Dd    64
#define Gg    4
#define KVW   512
#define Mrows (Bb*Tt)
#define YSIZE (Bb*Tt*Ee)
#define ATTSIZE ((size_t)Bb*Gg*HKVn*Tt*Tt)
#define WT_ROWS 2560

__device__ float g_l[Bb*HQn*Tt];
__device__ float g_ct[Tt*32];
__device__ float g_st[Tt*32];
__device__ float g_bqkv[1536];
__device__ __nv_bfloat16 g_xh[Mrows*Ee];
__device__ __nv_bfloat16 g_xl[Mrows*Ee];
__device__ __nv_bfloat16 g_yh[Mrows*Ee];    // Q split (post-rope)
__device__ __nv_bfloat16 g_yl[Mrows*Ee];
__device__ __nv_bfloat16 g_kvh[Bb*Tt*KVW];  // K(rope)|V split
__device__ __nv_bfloat16 g_kvl[Bb*Tt*KVW];
__device__ __nv_bfloat16 g_y2h[Mrows*Ee];   // attention output split
__device__ __nv_bfloat16 g_y2l[Mrows*Ee];
__device__ __nv_bfloat16 g_wth[WT_ROWS*Ee];
__device__ __nv_bfloat16 g_wtl[WT_ROWS*Ee];

// ============================ MMA / async helpers ============================
__device__ __forceinline__ uint32_t smem_to_u32(const void* p) {
    uint32_t a;
    asm("{ .reg .u64 t; cvta.to.shared.u64 t, %1; cvt.u32.u64 %0, t; }" : "=r"(a) : "l"(p));
    return a;
}
__device__ __forceinline__ void ldsm_x4(uint32_t& r0, uint32_t& r1, uint32_t& r2, uint32_t& r3, uint32_t addr) {
    asm volatile("ldmatrix.sync.aligned.m8n8.x4.shared.b16 {%0,%1,%2,%3}, [%4];"
        : "=r"(r0), "=r"(r1), "=r"(r2), "=r"(r3) : "r"(addr));
}
__device__ __forceinline__ void mma16816(float* d, const uint32_t* a, const uint32_t* b) {
    asm volatile("mma.sync.aligned.m16n8k16.row.col.f32.bf16.bf16.f32 "
        "{%0,%1,%2,%3}, {%4,%5,%6,%7}, {%8,%9}, {%0,%1,%2,%3};"
        : "+f"(d[0]), "+f"(d[1]), "+f"(d[2]), "+f"(d[3])
        : "r"(a[0]), "r"(a[1]), "r"(a[2]), "r"(a[3]), "r"(b[0]), "r"(b[1]));
}
__device__ __forceinline__ void cpa16(uint32_t dst, const void* src) {
    asm volatile("cp.async.cg.shared.global [%0], [%1], 16;" :: "r"(dst), "l"(src));
}
#define CP_COMMIT() asm volatile("cp.async.commit_group;" ::: "memory")
#define CP_WAIT0()  asm volatile("cp.async.wait_group 0;" ::: "memory")

// split fp32 pair -> hi/lo bf16x2 stores
__device__ __forceinline__ void st_split2(__nv_bfloat16* dh, __nv_bfloat16* dl, size_t off, float a, float b) {
    __nv_bfloat16 h0 = __float2bfloat16_rn(a), h1 = __float2bfloat16_rn(b);
    __nv_bfloat162 hp; hp.x = h0; hp.y = h1;
    __nv_bfloat162 lp;
    lp.x = __float2bfloat16_rn(a - __bfloat162float(h0));
    lp.y = __float2bfloat16_rn(b - __bfloat162float(h1));
    *(__nv_bfloat162*)(dh + off) = hp;
    *(__nv_bfloat162*)(dl + off) = lp;
}

__device__ __forceinline__ float fast_exp(float x) {
    float y = x * 1.4426950408889634f;
    y = fminf(fmaxf(y, -120.0f), 120.0f);
    float fr = y + 12582912.0f;
    int   ni = __float_as_int(fr) - 0x4B400000;
    float f  = y - (fr - 12582912.0f);
    float p  = 1.3333558146e-3f;
    p = fmaf(p, f, 9.6181291071e-3f);
    p = fmaf(p, f, 5.5504108664e-2f);
    p = fmaf(p, f, 2.4022650696e-1f);
    p = fmaf(p, f, 6.9314718056e-1f);
    p = fmaf(p, f, 1.0f);
    return p * __int_as_float((ni + 127) << 23);
}

// ============================ fused prep: split x + rope table + pack bias ============================
__global__ void prep_all_kernel(const float* __restrict__ x,
                                const float* __restrict__ bq,
                                const float* __restrict__ bk,
                                const float* __restrict__ bv) {
    int idx = blockIdx.x * blockDim.x + threadIdx.x;
    if (idx < Mrows * Ee) {
        float v = x[idx];
        __nv_bfloat16 h = __float2bfloat16_rn(v);
        g_xh[idx] = h;
        g_xl[idx] = __float2bfloat16_rn(v - __bfloat162float(h));
    }
    if (idx < Tt * 32) {
        int t = idx >> 5, i = idx & 31;
        float theta = powf(10000.0f, -2.0f * (float)i / 64.0f);
        float ang   = (float)(t + 1) * theta;
        g_ct[idx] = cosf(ang);
        g_st[idx] = sinf(ang);
    }
    if (idx < 1536) {
        g_bqkv[idx] = (idx < 1024) ? bq[idx] : (idx < 1280 ? bk[idx - 1024] : bv[idx - 1280]);
    }
}

__global__ void transpose_split_kernel(const float* __restrict__ W, int N, int nbase) {
    __shared__ float tile[32][33];
    int n0 = blockIdx.x * 32, k0 = blockIdx.y * 32;
    int tx = threadIdx.x, ty = threadIdx.y;
    #pragma unroll
    for (int i = 0; i < 4; i++)
        tile[ty + 8 * i][tx] = W[(size_t)(k0 + ty + 8 * i) * N + n0 + tx];
    __syncthreads();
    #pragma unroll
    for (int i = 0; i < 4; i++) {
        float v = tile[tx][ty + 8 * i];
        __nv_bfloat16 h = __float2bfloat16_rn(v);
        size_t o = (size_t)(nbase + n0 + ty + 8 * i) * Ee + k0 + tx;
        g_wth[o] = h;
        g_wtl[o] = __float2bfloat16_rn(v - __bfloat162float(h));
    }
}

// ============================ shared GEMM mainloop (cp.async double-buffer) ============================
#define GEMM_SMEM 49152

struct GemmAcc { float d[2][8][4]; };

__device__ __forceinline__ void gemm_mainloop(
        GemmAcc& acc,
        const __nv_bfloat16* Ah, const __nv_bfloat16* Al,
        const __nv_bfloat16* Bh, const __nv_bfloat16* Bl,
        uint32_t sbase, int tid) {
    const int lane = tid & 31, wid = tid >> 5;
    const int mw = wid & 3, nw = wid >> 2;
    const int r = lane & 7, grp = lane >> 3;
    const int a_row = (grp & 1) * 8 + r;
    const int a_bo  = (grp >> 1) * 16;
    const int b_row = (grp >> 1) * 8 + r;
    const int b_bo  = (grp & 1) * 16;

    const size_t goff = (size_t)(tid >> 1) * Ee + (tid & 1) * 8;
    const uint32_t doff = (uint32_t)((tid >> 1) * 48 + (tid & 1) * 16);

    {
        cpa16(sbase + 0 * 6144 + doff, Ah + goff);
        cpa16(sbase + 1 * 6144 + doff, Al + goff);
        cpa16(sbase + 2 * 6144 + doff, Bh + goff);
        cpa16(sbase + 3 * 6144 + doff, Bl + goff);
        CP_COMMIT();
        CP_WAIT0();
        __syncthreads();
    }

    const int NC = Ee / 16;
    for (int c = 0; c < NC; c++) {
        const int buf = c & 1;
        if (c + 1 < NC) {
            uint32_t nb_ = sbase + (uint32_t)(1 - buf) * 24576;
            size_t o = goff + (size_t)(c + 1) * 16;
            cpa16(nb_ + 0 * 6144 + doff, Ah + o);
            cpa16(nb_ + 1 * 6144 + doff, Al + o);
            cpa16(nb_ + 2 * 6144 + doff, Bh + o);
            cpa16(nb_ + 3 * 6144 + doff, Bl + o);
            CP_COMMIT();
        }

        const uint32_t mbase = sbase + (uint32_t)buf * 24576;
        uint32_t afh[2][4], afl[2][4], bf[4][4];
        #pragma unroll
        for (int ma = 0; ma < 2; ma++) {
            int arow = mw * 32 + ma * 16 + a_row;
            ldsm_x4(afh[ma][0], afh[ma][1], afh[ma][2], afh[ma][3], mbase + 0 * 6144 + arow * 48 + a_bo);
            ldsm_x4(afl[ma][0], afl[ma][1], afl[ma][2], afl[ma][3], mbase + 1 * 6144 + arow * 48 + a_bo);
        }
        #pragma unroll
        for (int nb = 0; nb < 4; nb++) {
            int brow = nw * 64 + nb * 16 + b_row;
            ldsm_x4(bf[nb][0], bf[nb][1], bf[nb][2], bf[nb][3], mbase + 2 * 6144 + brow * 48 + b_bo);
        }
        #pragma unroll
        for (int ma = 0; ma < 2; ma++)
            #pragma unroll
            for (int nb = 0; nb < 8; nb++)
                mma16816(acc.d[ma][nb], afh[ma], &bf[nb >> 1][(nb & 1) * 2]);
        #pragma unroll
        for (int ma = 0; ma < 2; ma++)
            #pragma unroll
            for (int nb = 0; nb < 8; nb++)
                mma16816(acc.d[ma][nb], afl[ma], &bf[nb >> 1][(nb & 1) * 2]);
        #pragma unroll
        for (int nb = 0; nb < 4; nb++) {
            int brow = nw * 64 + nb * 16 + b_row;
            ldsm_x4(bf[nb][0], bf[nb][1], bf[nb][2], bf[nb][3], mbase + 3 * 6144 + brow * 48 + b_bo);
        }
        #pragma unroll
        for (int ma = 0; ma < 2; ma++)
            #pragma unroll
            for (int nb = 0; nb < 8; nb++)
                mma16816(acc.d[ma][nb], afh[ma], &bf[nb >> 1][(nb & 1) * 2]);

        if (c + 1 < NC) {
            CP_WAIT0();
            __syncthreads();
        }
    }
}

// ============================ fused QKV GEMM + RoPE + split epilogue ============================
__global__ void __launch_bounds__(256) gemm_qkv_kernel() {
    extern __shared__ char smd[];
    const int tid = threadIdx.x;
    const int lane = tid & 31, wid = tid >> 5;
    const int mw = wid & 3, nw = wid >> 2;
    const int n0 = blockIdx.x * 128, m0 = blockIdx.y * 128;
    const uint32_t sbase = smem_to_u32(smd);

    GemmAcc acc = {};
    gemm_mainloop(acc,
                  g_xh + (size_t)m0 * Ee, g_xl + (size_t)m0 * Ee,
                  g_wth + (size_t)n0 * Ee, g_wtl + (size_t)n0 * Ee,
                  sbase, tid);

    const int erow = lane >> 2, ecol = (lane & 3) * 2;
    #pragma unroll
    for (int ma = 0; ma < 2; ma++) {
        int row = m0 + mw * 32 + ma * 16 + erow;
        int t0 = row & (Tt - 1), t1 = (row + 8) & (Tt - 1);
        #pragma unroll
        for (int nb = 0; nb < 4; nb++) {
            int c = n0 + nw * 64 + nb * 8 + ecol;
            float v0 = acc.d[ma][nb][0]     + g_bqkv[c];
            float v1 = acc.d[ma][nb][1]     + g_bqkv[c + 1];
            float v2 = acc.d[ma][nb][2]     + g_bqkv[c];
            float v3 = acc.d[ma][nb][3]     + g_bqkv[c + 1];
            float w0 = acc.d[ma][nb + 4][0] + g_bqkv[c + 32];
            float w1 = acc.d[ma][nb + 4][1] + g_bqkv[c + 33];
            float w2 = acc.d[ma][nb + 4][2] + g_bqkv[c + 32];
            float w3 = acc.d[ma][nb + 4][3] + g_bqkv[c + 33];

            if (c < 1280) {
                int i0 = c & 63, i1 = i0 + 1;
                float c00 = g_ct[t0 * 32 + i0], s00 = g_st[t0 * 32 + i0];
                float c01 = g_ct[t0 * 32 + i1], s01 = g_st[t0 * 32 + i1];
                float c10 = g_ct[t1 * 32 + i0], s10 = g_st[t1 * 32 + i0];
                float c11 = g_ct[t1 * 32 + i1], s11 = g_st[t1 * 32 + i1];
                float a;
                a = v0; v0 = fmaf(a, c00, -w0 * s00); w0 = fmaf(w0, c00, a * s00);
                a = v1; v1 = fmaf(a, c01, -w1 * s01); w1 = fmaf(w1, c01, a * s01);
                a = v2; v2 = fmaf(a, c10, -w2 * s10); w2 = fmaf(w2, c10, a * s10);
                a = v3; v3 = fmaf(a, c11, -w3 * s11); w3 = fmaf(w3, c11, a * s11);
            }

            __nv_bfloat16 *dh, *dl; int stride, cc;
            if (c < 1024) { dh = g_yh;  dl = g_yl;  stride = Ee;  cc = c; }
            else          { dh = g_kvh; dl = g_kvl; stride = KVW; cc = c - 1024; }
            st_split2(dh, dl, (size_t)row * stride + cc,            v0, v1);
            st_split2(dh, dl, (size_t)(row + 8) * stride + cc,      v2, v3);
            st_split2(dh, dl, (size_t)row * stride + cc + 32,       w0, w1);
            st_split2(dh, dl, (size_t)(row + 8) * stride + cc + 32, w2, w3);
        }
    }
}

// ============================ fused O-projection GEMM + att normalize ============================
// blocks [0,256): O-GEMM tiles (8 n-tiles x 32 m-tiles); blocks [256,...): one att row each.
__global__ void __launch_bounds__(256) gemm_o_norm_kernel(const float* __restrict__ bias,
                                                          float* __restrict__ C,
                                                          float* __restrict__ att) {
    const int bx = blockIdx.x;
    if (bx >= 256) {
        // ---- normalize att row ----
        int row = bx - 256;
        int q = row & (Tt - 1);
        int h = (row >> 11) & 3;
        int g = (row >> 13) & 3;
        int b = row >> 15;
        int hq = h * Gg + g;
        float inv = 1.0f / g_l[(b * HQn + hq) * Tt + q];
        float* p = att + (size_t)row * Tt;
        for (int k0 = threadIdx.x * 4; k0 < Tt; k0 += blockDim.x * 4) {
            float4 v;
            if (k0 <= q) {
                v = *(float4*)(p + k0);
                v.x = v.x * inv;
                v.y = (k0 + 1 <= q) ? v.y * inv : 0.0f;
                v.z = (k0 + 2 <= q) ? v.z * inv : 0.0f;
                v.w = (k0 + 3 <= q) ? v.w * inv : 0.0f;
            } else {
                v = make_float4(0.0f, 0.0f, 0.0f, 0.0f);
            }
            *(float4*)(p + k0) = v;
        }
        return;
    }

    // ---- O-GEMM tile ----
    extern __shared__ char smd[];
    const int tid = threadIdx.x;
    const int lane = tid & 31, wid = tid >> 5;
    const int mw = wid & 3, nw = wid >> 2;
    const int n0 = (bx & 7) * 128, m0 = (bx >> 3) * 128;
    const uint32_t sbase = smem_to_u32(smd);

    GemmAcc acc = {};
    gemm_mainloop(acc,
                  g_y2h + (size_t)m0 * Ee, g_y2l + (size_t)m0 * Ee,
                  g_wth + (size_t)(1536 + n0) * Ee, g_wtl + (size_t)(1536 + n0) * Ee,
                  sbase, tid);

    const int erow = lane >> 2, ecol = (lane & 3) * 2;
    #pragma unroll
    for (int ma = 0; ma < 2; ma++) {
        int row0 = m0 + mw * 32 + ma * 16 + erow;
        #pragma unroll
        for (int nb = 0; nb < 8; nb++) {
            int col = n0 + nw * 64 + nb * 8 + ecol;
            float b0v = bias[col], b1v = bias[col + 1];
            float* p  = C + (size_t)row0 * Ee + col;
            float* p2 = p + (size_t)8 * Ee;
            p[0]  = acc.d[ma][nb][0] + b0v;  p[1]  = acc.d[ma][nb][1] + b1v;
            p2[0] = acc.d[ma][nb][2] + b0v;  p2[1] = acc.d[ma][nb][3] + b1v;
        }
    }
}

// ============================ MMA attention ============================
#define ATTN_SMEM 142336

__global__ void __launch_bounds__(256) attn_mma_kernel(float* __restrict__ att, int write_att) {
    extern __shared__ char dsm[];
    __nv_bfloat16* sQh = (__nv_bfloat16*)(dsm);
    __nv_bfloat16* sQl = (__nv_bfloat16*)(dsm + 18432);
    __nv_bfloat16* sPh = (__nv_bfloat16*)(dsm + 36864);
    __nv_bfloat16* sPl = (__nv_bfloat16*)(dsm + 71680);
    __nv_bfloat16* sVh = (__nv_bfloat16*)(dsm + 106496);
    __nv_bfloat16* sVl = (__nv_bfloat16*)(dsm + 123904);
    float* sLs = (float*)(dsm + 141312);

    const int tid = threadIdx.x, lane = tid & 31, wid = tid >> 5;
    const int mw = wid & 3, nw = wid >> 2;
    const int qt = (Tt / 128 - 1) - blockIdx.x;   // heavy tiles first
    const int hq = blockIdx.y, b = blockIdx.z;
    const int h = hq >> 2, g = hq & 3;
    const int q0 = qt * 128;

    const uint32_t uQh = smem_to_u32(sQh), uQl = smem_to_u32(sQl);
    const uint32_t uPh = smem_to_u32(sPh), uPl = smem_to_u32(sPl);
    const uint32_t uVh = smem_to_u32(sVh), uVl = smem_to_u32(sVl);

    const int r = lane & 7, grp = lane >> 3;
    const int a_row = (grp & 1) * 8 + r, a_bo = (grp >> 1) * 16;
    const int b_row = (grp >> 1) * 8 + r, b_bo = (grp & 1) * 16;
    const int erow = lane >> 2, ecol = (lane & 3) * 2;

    for (int i = tid; i < 1024; i += 256) {
        int row = i >> 3, seg = i & 7;
        size_t go = ((size_t)(b * Tt + q0 + row)) * Ee + hq * Dd + seg * 8;
        *(uint4*)(sQh + row * 72 + seg * 8) = *(const uint4*)(g_yh + go);
        *(uint4*)(sQl + row * 72 + seg * 8) = *(const uint4*)(g_yl + go);
    }

    float dy[2][4][4] = {};
    float lsl[2][2] = {};
    const size_t attRow0 = (size_t)((b * Gg + g) * HKVn + h) * Tt;

    const int nkt = qt + 1;
    for (int kt = 0; kt < nkt; kt++) {
        const int k0 = kt * 128;
        for (int i = tid; i < 1024; i += 256) {
            int row = i >> 3, seg = i & 7;
            size_t go = ((size_t)(b * Tt + k0 + row)) * KVW + h * Dd + seg * 8;
            *(uint4*)(sPh + row * 72 + seg * 8) = *(const uint4*)(g_kvh + go);
            *(uint4*)(sPl + row * 72 + seg * 8) = *(const uint4*)(g_kvl + go);
        }
        for (int i = tid; i < 1024; i += 256) {
            int key = i & 127, seg = i >> 7;
            size_t go = ((size_t)(b * Tt + k0 + key)) * KVW + 256 + h * Dd + seg * 8;
            uint4 vh4 = *(const uint4*)(g_kvh + go);
            uint4 vl4 = *(const uint4*)(g_kvl + go);
            const __nv_bfloat16* ph = (const __nv_bfloat16*)&vh4;
            const __nv_bfloat16* pl = (const __nv_bfloat16*)&vl4;
            #pragma unroll
            for (int j = 0; j < 8; j++) {
                sVh[(seg * 8 + j) * 136 + key] = ph[j];
                sVl[(seg * 8 + j) * 136 + key] = pl[j];
            }
        }
        __syncthreads();

        float ds[2][8][4] = {};
        #pragma unroll
        for (int c = 0; c < 4; c++) {
            uint32_t qh[2][4], ql[2][4], kb[4][4];
            #pragma unroll
            for (int ma = 0; ma < 2; ma++) {
                uint32_t ar = (uint32_t)((mw * 32 + ma * 16 + a_row) * 144 + c * 32 + a_bo);
                ldsm_x4(qh[ma][0], qh[ma][1], qh[ma][2], qh[ma][3], uQh + ar);
                ldsm_x4(ql[ma][0], ql[ma][1], ql[ma][2], ql[ma][3], uQl + ar);
            }
            #pragma unroll
            for (int nt = 0; nt < 4; nt++) {
                uint32_t br = (uint32_t)((nw * 64 + nt * 16 + b_row) * 144 + c * 32 + b_bo);
                ldsm_x4(kb[nt][0], kb[nt][1], kb[nt][2], kb[nt][3], uPh + br);
            }
            #pragma unroll
            for (int ma = 0; ma < 2; ma++)
                #pragma unroll
                for (int nb = 0; nb < 8; nb++)
                    mma16816(ds[ma][nb], qh[ma], &kb[nb >> 1][(nb & 1) * 2]);
            #pragma unroll
            for (int ma = 0; ma < 2; ma++)
                #pragma unroll
                for (int nb = 0; nb < 8; nb++)
                    mma16816(ds[ma][nb], ql[ma], &kb[nb >> 1][(nb & 1) * 2]);
            #pragma unroll
            for (int nt = 0; nt < 4; nt++) {
                uint32_t br = (uint32_t)((nw * 64 + nt * 16 + b_row) * 144 + c * 32 + b_bo);
                ldsm_x4(kb[nt][0], kb[nt][1], kb[nt][2], kb[nt][3], uPl + br);
            }
            #pragma unroll
            for (int ma = 0; ma < 2; ma++)
                #pragma unroll
                for (int nb = 0; nb < 8; nb++)
                    mma16816(ds[ma][nb], qh[ma], &kb[nb >> 1][(nb & 1) * 2]);
        }
        __syncthreads();

        const bool diag = (kt == qt);
        #pragma unroll
        for (int ma = 0; ma < 2; ma++) {
            #pragma unroll
            for (int hh = 0; hh < 2; hh++) {
                int lrow = mw * 32 + ma * 16 + erow + 8 * hh;
                int qrow = q0 + lrow;
                float lacc = 0.0f;
                #pragma unroll
                for (int nb = 0; nb < 8; nb++) {
                    int lcol = nw * 64 + nb * 8 + ecol;
                    int kcol = k0 + lcol;
                    float e0 = fast_exp(ds[ma][nb][hh * 2 + 0] * 0.125f);
                    float e1 = fast_exp(ds[ma][nb][hh * 2 + 1] * 0.125f);
                    if (diag) {
                        if (kcol > qrow)     e0 = 0.0f;
                        if (kcol + 1 > qrow) e1 = 0.0f;
                    }
                    lacc += e0 + e1;
                    if (write_att)
                        *(float2*)(att + (attRow0 + qrow) * Tt + kcol) = make_float2(e0, e1);
                    __nv_bfloat16 h0 = __float2bfloat16_rn(e0), h1 = __float2bfloat16_rn(e1);
                    __nv_bfloat16 l0 = __float2bfloat16_rn(e0 - __bfloat162float(h0));
                    __nv_bfloat16 l1 = __float2bfloat16_rn(e1 - __bfloat162float(h1));
                    __nv_bfloat162 hp; hp.x = h0; hp.y = h1;
                    __nv_bfloat162 lp; lp.x = l0; lp.y = l1;
                    *(__nv_bfloat162*)(sPh + lrow * 136 + lcol) = hp;
                    *(__nv_bfloat162*)(sPl + lrow * 136 + lcol) = lp;
                }
                lsl[ma][hh] += lacc;
            }
        }
        __syncthreads();

        #pragma unroll
        for (int c = 0; c < 8; c++) {
            uint32_t ph[2][4], pl[2][4], vb[2][4];
            #pragma unroll
            for (int ma = 0; ma < 2; ma++) {
                uint32_t ar = (uint32_t)((mw * 32 + ma * 16 + a_row) * 272 + c * 32 + a_bo);
                ldsm_x4(ph[ma][0], ph[ma][1], ph[ma][2], ph[ma][3], uPh + ar);
                ldsm_x4(pl[ma][0], pl[ma][1], pl[ma][2], pl[ma][3], uPl + ar);
            }
            #pragma unroll
            for (int nt = 0; nt < 2; nt++) {
                uint32_t br = (uint32_t)((nw * 32 + nt * 16 + b_row) * 272 + c * 32 + b_bo);
                ldsm_x4(vb[nt][0], vb[nt][1], vb[nt][2], vb[nt][3], uVh + br);
            }
            #pragma unroll
            for (int ma = 0; ma < 2; ma++)
                #pragma unroll
                for (int nb = 0; nb < 4; nb++) {
                    mma16816(dy[ma][nb], ph[ma], &vb[nb >> 1][(nb & 1) * 2]);
                    mma16816(dy[ma][nb], pl[ma], &vb[nb >> 1][(nb & 1) * 2]);
                }
            #pragma unroll
            for (int nt = 0; nt < 2; nt++) {
                uint32_t br = (uint32_t)((nw * 32 + nt * 16 + b_row) * 272 + c * 32 + b_bo);
                ldsm_x4(vb[nt][0], vb[nt][1], vb[nt][2], vb[nt][3], uVl + br);
            }
            #pragma unroll
            for (int ma = 0; ma < 2; ma++)
                #pragma unroll
                for (int nb = 0; nb < 4; nb++)
                    mma16816(dy[ma][nb], ph[ma], &vb[nb >> 1][(nb & 1) * 2]);
        }
        __syncthreads();
    }

    #pragma unroll
    for (int ma = 0; ma < 2; ma++)
        #pragma unroll
        for (int hh = 0; hh < 2; hh++) {
            float v = lsl[ma][hh];
            v += __shfl_xor_sync(0xffffffffu, v, 1);
            v += __shfl_xor_sync(0xffffffffu, v, 2);
            if ((lane & 3) == 0)
                sLs[nw * 128 + mw * 32 + ma * 16 + erow + 8 * hh] = v;
        }
    __syncthreads();
    #pragma unroll
    for (int ma = 0; ma < 2; ma++)
        #pragma unroll
        for (int hh = 0; hh < 2; hh++) {
            int lrow = mw * 32 + ma * 16 + erow + 8 * hh;
            float tot = sLs[lrow] + sLs[128 + lrow];
            float inv = 1.0f / tot;
            if (nw == 0 && (lane & 3) == 0)
                g_l[(b * HQn + hq) * Tt + q0 + lrow] = tot;
            #pragma unroll
            for (int nb = 0; nb < 4; nb++) {
                int col = hq * Dd + nw * 32 + nb * 8 + ecol;
                st_split2(g_y2h, g_y2l,
                          ((size_t)(b * Tt + q0 + lrow)) * Ee + col,
                          dy[ma][nb][hh * 2] * inv, dy[ma][nb][hh * 2 + 1] * inv);
            }
        }
}

// ============================ launch ============================
extern "C" void kernel_launch(void* const* d_in, const int* in_sizes, int n_in,
                              void* d_out, int out_size) {
    (void)in_sizes; (void)n_in;
    const float* x  = (const float*)d_in[0];
    const float* Wq = (const float*)d_in[2];
    const float* bq = (const float*)d_in[3];
    const float* Wk = (const float*)d_in[4];
    const float* bk = (const float*)d_in[5];
    const float* Wv = (const float*)d_in[6];
    const float* bv = (const float*)d_in[7];
    const float* Wo = (const float*)d_in[8];
    const float* bo = (const float*)d_in[9];

    float* out = (float*)d_out;
    const int has_att = ((size_t)out_size >= (size_t)YSIZE + ATTSIZE) ? 1 : 0;
    float* att = out + (size_t)YSIZE;

    cudaFuncSetAttribute(attn_mma_kernel,   cudaFuncAttributeMaxDynamicSharedMemorySize, ATTN_SMEM);
    cudaFuncSetAttribute(gemm_qkv_kernel,   cudaFuncAttributeMaxDynamicSharedMemorySize, GEMM_SMEM);
    cudaFuncSetAttribute(gemm_o_norm_kernel, cudaFuncAttributeMaxDynamicSharedMemorySize, GEMM_SMEM);

    // 1: fused prep (split x + rope table + bias pack)
    prep_all_kernel<<<(Mrows * Ee + 255) / 256, 256>>>(x, bq, bk, bv);
    // 2-5: weight transpose+split
    transpose_split_kernel<<<dim3(Ee / 32,  Ee / 32), dim3(32, 8)>>>(Wq, Ee,  0);
    transpose_split_kernel<<<dim3(256 / 32, Ee / 32), dim3(32, 8)>>>(Wk, 256, 1024);
    transpose_split_kernel<<<dim3(256 / 32, Ee / 32), dim3(32, 8)>>>(Wv, 256, 1280);
    transpose_split_kernel<<<dim3(Ee / 32,  Ee / 32), dim3(32, 8)>>>(Wo, Ee,  1536);
    // 6: fused QKV projection + rope + split epilogue   <-- ncu -s 5 -c 1 captures this
    gemm_qkv_kernel<<<dim3(1536 / 128, Mrows / 128), 256, GEMM_SMEM>>>();
    // 7: attention
    attn_mma_kernel<<<dim3(Tt / 128, HQn, Bb), 256, ATTN_SMEM>>>(att, has_att);
    // 8: fused O-projection + att normalize (concurrent)
    {
        int nblk = 256 + (has_att ? Bb * Gg * HKVn * Tt : 0);
        gemm_o_norm_kernel<<<nblk, 256, GEMM_SMEM>>>(bo, out, att);
    }
}